// round 1
// baseline (speedup 1.0000x reference)
#include <cuda_runtime.h>

// SPADE: InstanceNorm2d(affine=False) + per-pixel class-conditional affine.
// Shapes (fixed by problem): x[8,128,256,256] f32, segmap[8,20,256,256] f32,
// weight[20,128] f32, bias[20,128] f32, out[8,128,256,256] f32.

#define N_   8
#define C_   128
#define H_   256
#define W_   256
#define L_   20
#define HW_  (H_ * W_)      // 65536
#define NC_  (N_ * C_)      // 1024
#define EPS_ 1e-5f

// Per-(n,c) statistics: .x = mean, .y = rsqrt(var + eps)
__device__ float2 g_stats[NC_];

// ---------------------------------------------------------------------------
// Kernel 1: per-(n,c) mean / inv-std. One block per plane (65536 floats).
// ---------------------------------------------------------------------------
__global__ void __launch_bounds__(256) spade_stats_kernel(const float* __restrict__ x) {
    const int nc = blockIdx.x;
    const float4* __restrict__ p = reinterpret_cast<const float4*>(x + (size_t)nc * HW_);

    float s = 0.f, s2 = 0.f;
    #pragma unroll 4
    for (int i = threadIdx.x; i < HW_ / 4; i += 256) {
        float4 v = __ldg(p + i);
        s  += (v.x + v.y) + (v.z + v.w);
        s2 += v.x * v.x + v.y * v.y + v.z * v.z + v.w * v.w;
    }

    // warp reduce
    #pragma unroll
    for (int o = 16; o > 0; o >>= 1) {
        s  += __shfl_down_sync(0xFFFFFFFFu, s,  o);
        s2 += __shfl_down_sync(0xFFFFFFFFu, s2, o);
    }

    __shared__ float ss[8], ss2[8];
    const int wid = threadIdx.x >> 5, lid = threadIdx.x & 31;
    if (lid == 0) { ss[wid] = s; ss2[wid] = s2; }
    __syncthreads();

    if (threadIdx.x == 0) {
        float ts = 0.f, ts2 = 0.f;
        #pragma unroll
        for (int i = 0; i < 8; i++) { ts += ss[i]; ts2 += ss2[i]; }
        const float inv_hw = 1.0f / (float)HW_;
        float mean = ts * inv_hw;
        float var  = ts2 * inv_hw - mean * mean;
        if (var < 0.f) var = 0.f;  // numerical safety
        g_stats[nc] = make_float2(mean, rsqrtf(var + EPS_));
    }
}

// ---------------------------------------------------------------------------
// Kernel 2: argmax(segmap) per pixel + normalize + class-conditional affine.
// Block = 256 threads handles HPB=4 rows of one image (one thread per column,
// one cls per (row, col)). (w,b) merged into padded smem table: stride 129
// float2 -> bank = 2*((cls + c) mod 16), so divergent-cls gathers are at most
// 2-way bank conflicted instead of a 20-sector L1 gather.
// ---------------------------------------------------------------------------
#define HPB 4
#define WB_STRIDE 129

__global__ void __launch_bounds__(256) spade_apply_kernel(
    const float* __restrict__ x,
    const float* __restrict__ seg,
    const float* __restrict__ wgt,
    const float* __restrict__ bia,
    float* __restrict__ out)
{
    __shared__ float2 s_wb[L_ * WB_STRIDE];   // (weight, bias) per (cls, c)
    __shared__ float2 s_ms[C_];               // (mean, invstd) per c for this n

    const int blk  = blockIdx.x;              // 0 .. N*H/HPB - 1 (= 2047? no: 512)
    const int n    = blk / (H_ / HPB);        // image index
    const int h0   = (blk % (H_ / HPB)) * HPB;
    const int wcol = threadIdx.x;             // 0..255

    // Stage merged (w,b) table into padded smem.
    for (int i = threadIdx.x; i < L_ * C_; i += 256) {
        int l = i >> 7, c = i & (C_ - 1);
        s_wb[l * WB_STRIDE + c] = make_float2(wgt[i], bia[i]);
    }
    // Stage per-channel stats for this image.
    if (threadIdx.x < C_)
        s_ms[threadIdx.x] = g_stats[n * C_ + threadIdx.x];

    // Per-pixel argmax over 20 segmap channels (first-index tie semantics
    // via strict '>' — matches jnp.argmax; ties measure-zero anyway).
    int cls[HPB];
    {
        const float* __restrict__ segn = seg + (size_t)n * L_ * HW_;
        #pragma unroll
        for (int r = 0; r < HPB; r++) {
            const int pix = (h0 + r) * W_ + wcol;
            float best = __ldg(segn + pix);
            int   bi   = 0;
            #pragma unroll
            for (int l = 1; l < L_; l++) {
                float v = __ldg(segn + (size_t)l * HW_ + pix);
                if (v > best) { best = v; bi = l; }
            }
            cls[r] = bi;
        }
    }
    __syncthreads();

    const float* __restrict__ xn = x   + (size_t)n * C_ * HW_;
    float*       __restrict__ on = out + (size_t)n * C_ * HW_;

    #pragma unroll 2
    for (int c = 0; c < C_; c++) {
        const float2 ms = s_ms[c];           // broadcast (uniform address)
        float vx[HPB];
        int   off[HPB];
        #pragma unroll
        for (int r = 0; r < HPB; r++) {      // batch loads for MLP
            off[r] = c * HW_ + (h0 + r) * W_ + wcol;
            vx[r]  = __ldg(xn + off[r]);
        }
        #pragma unroll
        for (int r = 0; r < HPB; r++) {
            const float2 wb = s_wb[cls[r] * WB_STRIDE + c];
            const float norm = (vx[r] - ms.x) * ms.y;
            on[off[r]] = fmaf(norm, wb.x, wb.y);
        }
    }
}

// ---------------------------------------------------------------------------
extern "C" void kernel_launch(void* const* d_in, const int* in_sizes, int n_in,
                              void* d_out, int out_size) {
    const float* x   = (const float*)d_in[0];
    const float* seg = (const float*)d_in[1];
    const float* wgt = (const float*)d_in[2];
    const float* bia = (const float*)d_in[3];
    float* out = (float*)d_out;

    spade_stats_kernel<<<NC_, 256>>>(x);
    spade_apply_kernel<<<(N_ * H_) / HPB, 256>>>(x, seg, wgt, bia, out);
}

// round 2
// speedup vs baseline: 1.1100x; 1.1100x over previous
#include <cuda_runtime.h>

// SPADE: InstanceNorm2d(affine=False) + per-pixel class-conditional affine.
// x[8,128,256,256] f32, segmap[8,20,256,256] f32, weight/bias[20,128] f32.

#define N_   8
#define C_   128
#define H_   256
#define W_   256
#define L_   20
#define HW_  (H_ * W_)      // 65536
#define NC_  (N_ * C_)      // 1024
#define EPS_ 1e-5f

// Per-(n,c) stats: .x = mean, .y = rsqrt(var+eps)
__device__ float2 g_stats[NC_];
// Per-pixel argmax class id
__device__ unsigned char g_cls[N_ * HW_];   // 512 KB scratch

// ---------------------------------------------------------------------------
// Kernel 1: per-(n,c) mean / inv-std. One block per plane.
// ---------------------------------------------------------------------------
__global__ void __launch_bounds__(256) spade_stats_kernel(const float* __restrict__ x) {
    const int nc = blockIdx.x;
    const float4* __restrict__ p = reinterpret_cast<const float4*>(x + (size_t)nc * HW_);

    float s = 0.f, s2 = 0.f;
    #pragma unroll 8
    for (int i = threadIdx.x; i < HW_ / 4; i += 256) {
        float4 v = __ldcs(p + i);
        s  += (v.x + v.y) + (v.z + v.w);
        s2 += v.x * v.x + v.y * v.y + v.z * v.z + v.w * v.w;
    }

    #pragma unroll
    for (int o = 16; o > 0; o >>= 1) {
        s  += __shfl_down_sync(0xFFFFFFFFu, s,  o);
        s2 += __shfl_down_sync(0xFFFFFFFFu, s2, o);
    }

    __shared__ float ss[8], ss2[8];
    const int wid = threadIdx.x >> 5, lid = threadIdx.x & 31;
    if (lid == 0) { ss[wid] = s; ss2[wid] = s2; }
    __syncthreads();

    if (threadIdx.x == 0) {
        float ts = 0.f, ts2 = 0.f;
        #pragma unroll
        for (int i = 0; i < 8; i++) { ts += ss[i]; ts2 += ss2[i]; }
        const float inv_hw = 1.0f / (float)HW_;
        float mean = ts * inv_hw;
        float var  = ts2 * inv_hw - mean * mean;
        if (var < 0.f) var = 0.f;
        g_stats[nc] = make_float2(mean, rsqrtf(var + EPS_));
    }
}

// ---------------------------------------------------------------------------
// Kernel 2: per-pixel argmax over the 20 segmap planes -> uchar class map.
// Thread = 4 adjacent pixels (float4 per plane). Fully coalesced single pass.
// ---------------------------------------------------------------------------
__global__ void __launch_bounds__(256) spade_argmax_kernel(const float* __restrict__ seg) {
    const int idx = blockIdx.x * 256 + threadIdx.x;     // over N*HW/4
    const int n   = idx / (HW_ / 4);
    const int p4  = idx - n * (HW_ / 4);
    const float4* __restrict__ s =
        reinterpret_cast<const float4*>(seg + (size_t)n * L_ * HW_) + p4;

    float4 best = __ldcs(s);
    int b0 = 0, b1 = 0, b2 = 0, b3 = 0;
    #pragma unroll
    for (int l = 1; l < L_; l++) {
        float4 v = __ldcs(s + (size_t)l * (HW_ / 4));
        if (v.x > best.x) { best.x = v.x; b0 = l; }
        if (v.y > best.y) { best.y = v.y; b1 = l; }
        if (v.z > best.z) { best.z = v.z; b2 = l; }
        if (v.w > best.w) { best.w = v.w; b3 = l; }
    }
    uchar4 r = make_uchar4((unsigned char)b0, (unsigned char)b1,
                           (unsigned char)b2, (unsigned char)b3);
    *reinterpret_cast<uchar4*>(g_cls + (size_t)n * HW_ + p4 * 4) = r;
}

// ---------------------------------------------------------------------------
// Kernel 3: normalize + class-conditional affine.
// Block = 256 threads = 4 rows x 256 cols (thread = float4), one channel
// group (64 of 128 channels). Grid = N * (H/4) * 2 = 1024 blocks.
// (w,b) in padded smem (stride 65 float2): divergent-cls gather is <=2-way
// bank conflicted. Channel loop unrolled x4 for MLP.
// ---------------------------------------------------------------------------
#define CGRP 64
#define WB_STRIDE 65

__global__ void __launch_bounds__(256) spade_apply_kernel(
    const float* __restrict__ x,
    const float* __restrict__ wgt,
    const float* __restrict__ bia,
    float* __restrict__ out)
{
    __shared__ float2 s_wb[L_ * WB_STRIDE];   // (weight, bias) for this cgroup
    __shared__ float2 s_ms[CGRP];             // (mean, invstd) for this cgroup

    const int b   = blockIdx.x;
    const int cg  = b & 1;                    // channel group 0/1
    const int t   = b >> 1;
    const int n   = t >> 6;                   // t / 64
    const int h0  = (t & 63) << 2;            // 4-row slab
    const int tid = threadIdx.x;
    const int c0  = cg * CGRP;

    // Stage merged (w,b) for our 64 channels.
    for (int i = tid; i < L_ * CGRP; i += 256) {
        int l = i >> 6, c = i & (CGRP - 1);
        s_wb[l * WB_STRIDE + c] =
            make_float2(__ldg(wgt + l * C_ + c0 + c), __ldg(bia + l * C_ + c0 + c));
    }
    if (tid < CGRP)
        s_ms[tid] = g_stats[n * C_ + c0 + tid];

    // This thread's 4 pixels: row = tid/64, cols = (tid%64)*4 .. +3
    const int r    = tid >> 6;
    const int col4 = (tid & 63) << 2;
    const int pix  = (h0 + r) * W_ + col4;

    const uchar4 cl = *reinterpret_cast<const uchar4*>(g_cls + (size_t)n * HW_ + pix);
    const int i0 = cl.x * WB_STRIDE, i1 = cl.y * WB_STRIDE,
              i2 = cl.z * WB_STRIDE, i3 = cl.w * WB_STRIDE;
    __syncthreads();

    const float* __restrict__ xn = x   + (size_t)n * C_ * HW_ + (size_t)c0 * HW_ + pix;
    float*       __restrict__ on = out + (size_t)n * C_ * HW_ + (size_t)c0 * HW_ + pix;

    #pragma unroll 1
    for (int c = 0; c < CGRP; c += 4) {
        float4 v[4];
        #pragma unroll
        for (int u = 0; u < 4; u++)
            v[u] = __ldcs(reinterpret_cast<const float4*>(xn + (size_t)(c + u) * HW_));
        #pragma unroll
        for (int u = 0; u < 4; u++) {
            const int cc = c + u;
            const float2 ms = s_ms[cc];
            const float2 w0 = s_wb[i0 + cc];
            const float2 w1 = s_wb[i1 + cc];
            const float2 w2 = s_wb[i2 + cc];
            const float2 w3 = s_wb[i3 + cc];
            float4 o;
            o.x = fmaf((v[u].x - ms.x) * ms.y, w0.x, w0.y);
            o.y = fmaf((v[u].y - ms.x) * ms.y, w1.x, w1.y);
            o.z = fmaf((v[u].z - ms.x) * ms.y, w2.x, w2.y);
            o.w = fmaf((v[u].w - ms.x) * ms.y, w3.x, w3.y);
            __stcs(reinterpret_cast<float4*>(on + (size_t)cc * HW_), o);
        }
    }
}

// ---------------------------------------------------------------------------
extern "C" void kernel_launch(void* const* d_in, const int* in_sizes, int n_in,
                              void* d_out, int out_size) {
    const float* x   = (const float*)d_in[0];
    const float* seg = (const float*)d_in[1];
    const float* wgt = (const float*)d_in[2];
    const float* bia = (const float*)d_in[3];
    float* out = (float*)d_out;

    spade_stats_kernel<<<NC_, 256>>>(x);
    spade_argmax_kernel<<<(N_ * HW_ / 4) / 256, 256>>>(seg);
    spade_apply_kernel<<<N_ * (H_ / 4) * 2, 256>>>(x, wgt, bia, out);
}